// round 5
// baseline (speedup 1.0000x reference)
#include <cuda_runtime.h>

// ---------------------------------------------------------------------------
// GCN_dgl: 2-layer symmetric-normalized GCN + max-pool readout + linear head
//   x[50000,96] f32, src/dst[800000] i32, W1/W2[96,96], b1/b2[96], Wl[96,2], bl[2]
// Strategy (R4): GEMM-before-gather reordering (row-scaling commutes with @W,
// gather is linear) -> dense epilogues fold ns; gather epilogues fold
// nd/bias/relu (+maxpool for layer 2). CSR built in-graph; scan spine merged.
// ---------------------------------------------------------------------------

constexpr int NN = 50000;
constexpr int NE = 800000;
constexpr int D  = 96;
constexpr int SCAN_NB = (NN + 255) / 256;   // 196 scan blocks

// Scratch (allocation-free: __device__ globals)
__device__ int          g_degi_out[NN];
__device__ int          g_degi_in[NN];
__device__ float        g_norm_src[NN];
__device__ float        g_norm_dst[NN];
__device__ int          g_offs[NN + 1];     // CSR row offsets (by dst)
__device__ int          g_blocksums[SCAN_NB];
__device__ int          g_fill[NN];         // bucket fill counters
__device__ int          g_csr[NE];          // src index per CSR slot
__device__ float        g_xw[(size_t)NN * D];  // GEMM output (reused both layers)
__device__ float        g_h1[(size_t)NN * D];  // layer-1 activations (ns-prescaled)
__device__ unsigned int g_max[D];           // uint-ordered non-negative floats

// --- one-shot zeroing of all per-call accumulator state ---------------------
__global__ void zero_kernel() {
    int i = blockIdx.x * blockDim.x + threadIdx.x;
    if (i < NN) { g_degi_out[i] = 0; g_degi_in[i] = 0; g_fill[i] = 0; }
    if (i < D)  g_max[i] = 0u;
}

// --- degree histogram (int atomics) ----------------------------------------
__global__ void deg_kernel(const int* __restrict__ src, const int* __restrict__ dst) {
    int i = blockIdx.x * blockDim.x + threadIdx.x;
    if (i < NE) {
        atomicAdd(&g_degi_out[src[i]], 1);
        atomicAdd(&g_degi_in [dst[i]], 1);
    }
}

// --- scan pass 1: per-block exclusive scan of deg_in; norms fused here ------
__global__ void scan1_kernel() {
    __shared__ int sh[256];
    int t = threadIdx.x;
    int i = blockIdx.x * 256 + t;
    int v = (i < NN) ? g_degi_in[i] : 0;
    if (i < NN) {
        int dO = g_degi_out[i];
        g_norm_src[i] = (dO > 0) ? rsqrtf((float)dO) : 1.0f;
        g_norm_dst[i] = (v  > 0) ? rsqrtf((float)v)  : 1.0f;
    }
    sh[t] = v;
    __syncthreads();
    #pragma unroll
    for (int off = 1; off < 256; off <<= 1) {
        int a = (t >= off) ? sh[t - off] : 0;
        __syncthreads();
        sh[t] += a;
        __syncthreads();
    }
    if (i < NN) g_offs[i] = sh[t] - v;           // exclusive within block
    if (t == 255) g_blocksums[blockIdx.x] = sh[255];
}

// --- scan pass 2: every block redundantly scans the 196-entry spine ---------
__global__ void scan2_kernel() {
    __shared__ int sp[256];
    int t = threadIdx.x;
    int v = (t < SCAN_NB) ? g_blocksums[t] : 0;
    sp[t] = v;
    __syncthreads();
    #pragma unroll
    for (int off = 1; off < 256; off <<= 1) {
        int a = (t >= off) ? sp[t - off] : 0;
        __syncthreads();
        sp[t] += a;
        __syncthreads();
    }
    int prefix = (blockIdx.x > 0) ? sp[blockIdx.x - 1] : 0;   // exclusive spine
    int i = blockIdx.x * 256 + t;
    if (i < NN) g_offs[i] += prefix;
    if (i == 0) g_offs[NN] = NE;
}

// --- CSR bucket fill ---------------------------------------------------------
__global__ void fill_kernel(const int* __restrict__ src, const int* __restrict__ dst) {
    int e = blockIdx.x * blockDim.x + threadIdx.x;
    if (e < NE) {
        int d   = dst[e];
        int pos = g_offs[d] + atomicAdd(&g_fill[d], 1);
        g_csr[pos] = src[e];
    }
}

// --- dense GEMM: out = in @ W, epilogue per MODE -----------------------------
// MODE 0: out[n] = (in@W)[n] * norm_src[n]   (layer-1 pre-gather scaling)
// MODE 1: out[n] = (in@W)[n]                 (layer 2; in is already ns-scaled)
// Block (96,2): thread owns output feature j for 8 nodes; float4-staged rows.
template <int MODE>
__global__ void __launch_bounds__(192)
dense_kernel(const float* __restrict__ in, const float* __restrict__ W,
             float* __restrict__ out) {
    __shared__ float  Ws[D * D];                 // [k][j], conflict-free on j
    __shared__ float4 Rs4[2][8][D / 4];          // node rows as float4

    int j = threadIdx.x;              // 0..95 output feature
    int y = threadIdx.y;              // 0..1  node sub-group
    int t = y * 96 + j;

    for (int idx = t; idx < D * D; idx += 192) Ws[idx] = W[idx];

    int n0 = blockIdx.x * 16 + y * 8;
    #pragma unroll
    for (int m = 0; m < 8; m++) {
        int n = n0 + m;
        ((float*)&Rs4[y][m][0])[j] = (n < NN) ? in[(size_t)n * D + j] : 0.f;
    }
    __syncthreads();

    float acc[8];
    #pragma unroll
    for (int m = 0; m < 8; m++) acc[m] = 0.f;

    #pragma unroll 6
    for (int k4 = 0; k4 < D / 4; k4++) {
        float w0 = Ws[(4 * k4 + 0) * D + j];
        float w1 = Ws[(4 * k4 + 1) * D + j];
        float w2 = Ws[(4 * k4 + 2) * D + j];
        float w3 = Ws[(4 * k4 + 3) * D + j];
        #pragma unroll
        for (int m = 0; m < 8; m++) {
            float4 r = Rs4[y][m][k4];
            acc[m] = fmaf(r.x, w0, acc[m]);
            acc[m] = fmaf(r.y, w1, acc[m]);
            acc[m] = fmaf(r.z, w2, acc[m]);
            acc[m] = fmaf(r.w, w3, acc[m]);
        }
    }

    #pragma unroll
    for (int m = 0; m < 8; m++) {
        int n = n0 + m;
        if (n < NN) {
            float v = acc[m];
            if (MODE == 0) v *= g_norm_src[n];
            out[(size_t)n * D + j] = v;
        }
    }
}

// --- pull-gather + full layer epilogue ---------------------------------------
// agg[n] = sum_{s in N(n)} in[s]  (inputs are pre-scaled by ns)
// EPI 0: out[n][j] = relu(agg*nd[n] + b[j]) * ns[n]    (h1, prescaled for L2)
// EPI 1: v = relu(agg*nd[n] + b[j]) -> block smem max -> global atomicMax
// One warp per dst node; lane owns features {lane, lane+32, lane+64}.
template <int EPI>
__global__ void __launch_bounds__(256)
gather_kernel(const float* __restrict__ in, const float* __restrict__ b,
              float* __restrict__ out) {
    __shared__ unsigned int smax[D];
    int t = threadIdx.x;
    if (EPI == 1) {
        if (t < D) smax[t] = 0u;
        __syncthreads();
    }

    int gtid = blockIdx.x * 256 + t;
    int n    = gtid >> 5;
    int lane = gtid & 31;

    if (n < NN) {
        int p  = g_offs[n];
        int p1 = g_offs[n + 1];
        float a0 = 0.f, a1 = 0.f, a2 = 0.f;

        for (; p + 4 <= p1; p += 4) {             // unroll 4 for MLP
            int s0 = g_csr[p], s1 = g_csr[p + 1], s2 = g_csr[p + 2], s3 = g_csr[p + 3];
            const float* r0 = in + (size_t)s0 * D;
            const float* r1 = in + (size_t)s1 * D;
            const float* r2 = in + (size_t)s2 * D;
            const float* r3 = in + (size_t)s3 * D;
            a0 += r0[lane]      + r1[lane]      + r2[lane]      + r3[lane];
            a1 += r0[lane + 32] + r1[lane + 32] + r2[lane + 32] + r3[lane + 32];
            a2 += r0[lane + 64] + r1[lane + 64] + r2[lane + 64] + r3[lane + 64];
        }
        for (; p < p1; ++p) {
            const float* r = in + (size_t)g_csr[p] * D;
            a0 += r[lane]; a1 += r[lane + 32]; a2 += r[lane + 64];
        }

        float nd = g_norm_dst[n];
        float v0 = fmaxf(fmaf(a0, nd, b[lane]),      0.f);
        float v1 = fmaxf(fmaf(a1, nd, b[lane + 32]), 0.f);
        float v2 = fmaxf(fmaf(a2, nd, b[lane + 64]), 0.f);

        if (EPI == 0) {
            float ns = g_norm_src[n];
            float* o = out + (size_t)n * D;
            o[lane]      = v0 * ns;
            o[lane + 32] = v1 * ns;
            o[lane + 64] = v2 * ns;
        } else {
            // non-negative floats: uint ordering == float ordering
            atomicMax(&smax[lane],      __float_as_uint(v0));
            atomicMax(&smax[lane + 32], __float_as_uint(v1));
            atomicMax(&smax[lane + 64], __float_as_uint(v2));
        }
    }

    if (EPI == 1) {
        __syncthreads();
        if (t < D) atomicMax(&g_max[t], smax[t]);
    }
}

// --- head: out[1,2] = gmax @ Wl + bl ----------------------------------------
__global__ void final_kernel(const float* __restrict__ Wl,
                             const float* __restrict__ bl,
                             float* __restrict__ out) {
    int c = threadIdx.x;
    if (c < 2) {
        float acc = bl[c];
        #pragma unroll 8
        for (int k = 0; k < D; k++)
            acc += __uint_as_float(g_max[k]) * Wl[k * 2 + c];
        out[c] = acc;
    }
}

extern "C" void kernel_launch(void* const* d_in, const int* in_sizes, int n_in,
                              void* d_out, int out_size) {
    const float* x   = (const float*)d_in[0];
    const int*   src = (const int*)  d_in[1];
    const int*   dst = (const int*)  d_in[2];
    const float* W1  = (const float*)d_in[3];
    const float* b1  = (const float*)d_in[4];
    const float* W2  = (const float*)d_in[5];
    const float* b2  = (const float*)d_in[6];
    const float* Wl  = (const float*)d_in[7];
    const float* bl  = (const float*)d_in[8];
    float* out = (float*)d_out;

    // Host-visible device addresses (symbol names are NOT device ptrs on host)
    void *pxw, *ph1;
    cudaGetSymbolAddress(&pxw, g_xw);
    cudaGetSymbolAddress(&ph1, g_h1);
    float* xw = (float*)pxw;
    float* h1 = (float*)ph1;

    zero_kernel<<<(NN + 255) / 256, 256>>>();

    // Graph structure: degrees, norms (fused in scan1), CSR (dst-grouped)
    deg_kernel  <<<(NE + 255) / 256, 256>>>(src, dst);
    scan1_kernel<<<SCAN_NB, 256>>>();
    scan2_kernel<<<SCAN_NB, 256>>>();
    fill_kernel <<<(NE + 255) / 256, 256>>>(src, dst);

    int gblocks = (NN * 32 + 255) / 256;   // one warp per node
    int dblocks = (NN + 15) / 16;

    // Layer 1: xw = (x@W1)*ns;  h1 = relu(nd*gather(xw) + b1) * ns
    dense_kernel <0><<<dblocks, dim3(96, 2)>>>(x, W1, xw);
    gather_kernel<0><<<gblocks, 256>>>(xw, b1, h1);

    // Layer 2: xw = h1@W2 (h1 already ns-scaled); gather + fused maxpool
    dense_kernel <1><<<dblocks, dim3(96, 2)>>>(h1, W2, xw);
    gather_kernel<1><<<gblocks, 256>>>(xw, b2, nullptr);

    final_kernel<<<1, 32>>>(Wl, bl, out);
}

// round 6
// speedup vs baseline: 1.0054x; 1.0054x over previous
#include <cuda_runtime.h>

// ---------------------------------------------------------------------------
// GCN_dgl: 2-layer symmetric-normalized GCN + max-pool readout + linear head
// R5: (a) CSR build chain overlapped with x@W1 via side-stream fork/join,
//     (b) float4 gather (24 lanes x LDG.128 per row) with per-edge ns FMA,
//     (c) leaner zero kernel (fill/max zeroing folded into scan1).
// ---------------------------------------------------------------------------

constexpr int NN = 50000;
constexpr int NE = 800000;
constexpr int D  = 96;
constexpr int D4 = D / 4;                   // 24 float4 per row
constexpr int SCAN_NB = (NN + 255) / 256;   // 196 scan blocks

// Scratch (allocation-free: __device__ globals)
__device__ int          g_degi_out[NN];
__device__ int          g_degi_in[NN];
__device__ float        g_norm_src[NN];
__device__ float        g_norm_dst[NN];
__device__ int          g_offs[NN + 1];     // CSR row offsets (by dst)
__device__ int          g_blocksums[SCAN_NB];
__device__ int          g_fill[NN];         // bucket fill counters
__device__ int          g_csr[NE];          // src index per CSR slot
__device__ float        g_xw[(size_t)NN * D];  // GEMM output (reused)
__device__ float        g_h1[(size_t)NN * D];  // layer-1 activations (ns-prescaled)
__device__ unsigned int g_max[D];           // uint-ordered non-negative floats

// --- zero degree counters (head of CSR chain) --------------------------------
__global__ void zero_kernel() {
    int i = blockIdx.x * blockDim.x + threadIdx.x;
    if (i < NN) { g_degi_out[i] = 0; g_degi_in[i] = 0; }
}

// --- degree histogram ---------------------------------------------------------
__global__ void deg_kernel(const int* __restrict__ src, const int* __restrict__ dst) {
    int i = blockIdx.x * blockDim.x + threadIdx.x;
    if (i < NE) {
        atomicAdd(&g_degi_out[src[i]], 1);
        atomicAdd(&g_degi_in [dst[i]], 1);
    }
}

// --- scan pass 1: per-block exclusive scan of deg_in; norms/fill/max zeroed ---
__global__ void scan1_kernel() {
    __shared__ int sh[256];
    int t = threadIdx.x;
    int i = blockIdx.x * 256 + t;
    int v = (i < NN) ? g_degi_in[i] : 0;
    if (i < NN) {
        int dO = g_degi_out[i];
        g_norm_src[i] = (dO > 0) ? rsqrtf((float)dO) : 1.0f;
        g_norm_dst[i] = (v  > 0) ? rsqrtf((float)v)  : 1.0f;
        g_fill[i] = 0;                       // consumed by fill_kernel (later)
    }
    if (i < D) g_max[i] = 0u;                // consumed by gather<1> (later)
    sh[t] = v;
    __syncthreads();
    #pragma unroll
    for (int off = 1; off < 256; off <<= 1) {
        int a = (t >= off) ? sh[t - off] : 0;
        __syncthreads();
        sh[t] += a;
        __syncthreads();
    }
    if (i < NN) g_offs[i] = sh[t] - v;       // exclusive within block
    if (t == 255) g_blocksums[blockIdx.x] = sh[255];
}

// --- scan pass 2: every block redundantly scans the 196-entry spine -----------
__global__ void scan2_kernel() {
    __shared__ int sp[256];
    int t = threadIdx.x;
    int v = (t < SCAN_NB) ? g_blocksums[t] : 0;
    sp[t] = v;
    __syncthreads();
    #pragma unroll
    for (int off = 1; off < 256; off <<= 1) {
        int a = (t >= off) ? sp[t - off] : 0;
        __syncthreads();
        sp[t] += a;
        __syncthreads();
    }
    int prefix = (blockIdx.x > 0) ? sp[blockIdx.x - 1] : 0;   // exclusive spine
    int i = blockIdx.x * 256 + t;
    if (i < NN) g_offs[i] += prefix;
    if (i == 0) g_offs[NN] = NE;
}

// --- CSR bucket fill -----------------------------------------------------------
__global__ void fill_kernel(const int* __restrict__ src, const int* __restrict__ dst) {
    int e = blockIdx.x * blockDim.x + threadIdx.x;
    if (e < NE) {
        int d   = dst[e];
        int pos = g_offs[d] + atomicAdd(&g_fill[d], 1);
        g_csr[pos] = src[e];
    }
}

// --- dense GEMM: out = in @ W (plain; norms handled in gather) ------------------
// Block (96,2): thread owns output feature j for 8 nodes; float4-staged rows.
__global__ void __launch_bounds__(192)
dense_kernel(const float* __restrict__ in, const float* __restrict__ W,
             float* __restrict__ out) {
    __shared__ float  Ws[D * D];                 // [k][j], conflict-free on j
    __shared__ float4 Rs4[2][8][D4];             // node rows as float4

    int j = threadIdx.x;
    int y = threadIdx.y;
    int t = y * 96 + j;

    for (int idx = t; idx < D * D; idx += 192) Ws[idx] = W[idx];

    int n0 = blockIdx.x * 16 + y * 8;
    #pragma unroll
    for (int m = 0; m < 8; m++) {
        int n = n0 + m;
        ((float*)&Rs4[y][m][0])[j] = (n < NN) ? in[(size_t)n * D + j] : 0.f;
    }
    __syncthreads();

    float acc[8];
    #pragma unroll
    for (int m = 0; m < 8; m++) acc[m] = 0.f;

    #pragma unroll 6
    for (int k4 = 0; k4 < D4; k4++) {
        float w0 = Ws[(4 * k4 + 0) * D + j];
        float w1 = Ws[(4 * k4 + 1) * D + j];
        float w2 = Ws[(4 * k4 + 2) * D + j];
        float w3 = Ws[(4 * k4 + 3) * D + j];
        #pragma unroll
        for (int m = 0; m < 8; m++) {
            float4 r = Rs4[y][m][k4];
            acc[m] = fmaf(r.x, w0, acc[m]);
            acc[m] = fmaf(r.y, w1, acc[m]);
            acc[m] = fmaf(r.z, w2, acc[m]);
            acc[m] = fmaf(r.w, w3, acc[m]);
        }
    }

    #pragma unroll
    for (int m = 0; m < 8; m++) {
        int n = n0 + m;
        if (n < NN) out[(size_t)n * D + j] = acc[m];
    }
}

// --- pull-gather + layer epilogue (float4: lanes 0..23, one warp per node) ------
// EPI 0: agg = sum ns[s]*in[s];  out[n] = relu(agg*nd + b) * ns[n]
// EPI 1: agg = sum in[s] (pre-scaled); relu(agg*nd + b) -> smem max -> global max
template <int EPI>
__global__ void __launch_bounds__(256)
gather_kernel(const float4* __restrict__ in, const float4* __restrict__ b,
              float4* __restrict__ out) {
    __shared__ unsigned int smax[D];
    int t = threadIdx.x;
    if (EPI == 1) {
        if (t < D) smax[t] = 0u;
        __syncthreads();
    }

    int n    = (blockIdx.x * 256 + t) >> 5;
    int lane = t & 31;

    if (n < NN && lane < D4) {
        int p  = g_offs[n];
        int p1 = g_offs[n + 1];
        float4 a = make_float4(0.f, 0.f, 0.f, 0.f);

        for (; p + 4 <= p1; p += 4) {
            int s0 = g_csr[p], s1 = g_csr[p + 1], s2 = g_csr[p + 2], s3 = g_csr[p + 3];
            float4 r0 = in[(size_t)s0 * D4 + lane];
            float4 r1 = in[(size_t)s1 * D4 + lane];
            float4 r2 = in[(size_t)s2 * D4 + lane];
            float4 r3 = in[(size_t)s3 * D4 + lane];
            if (EPI == 0) {
                float n0 = g_norm_src[s0], n1 = g_norm_src[s1];
                float n2 = g_norm_src[s2], n3 = g_norm_src[s3];
                a.x = fmaf(r0.x, n0, fmaf(r1.x, n1, fmaf(r2.x, n2, fmaf(r3.x, n3, a.x))));
                a.y = fmaf(r0.y, n0, fmaf(r1.y, n1, fmaf(r2.y, n2, fmaf(r3.y, n3, a.y))));
                a.z = fmaf(r0.z, n0, fmaf(r1.z, n1, fmaf(r2.z, n2, fmaf(r3.z, n3, a.z))));
                a.w = fmaf(r0.w, n0, fmaf(r1.w, n1, fmaf(r2.w, n2, fmaf(r3.w, n3, a.w))));
            } else {
                a.x += r0.x + r1.x + r2.x + r3.x;
                a.y += r0.y + r1.y + r2.y + r3.y;
                a.z += r0.z + r1.z + r2.z + r3.z;
                a.w += r0.w + r1.w + r2.w + r3.w;
            }
        }
        for (; p < p1; ++p) {
            int s = g_csr[p];
            float4 r = in[(size_t)s * D4 + lane];
            if (EPI == 0) {
                float ns = g_norm_src[s];
                a.x = fmaf(r.x, ns, a.x); a.y = fmaf(r.y, ns, a.y);
                a.z = fmaf(r.z, ns, a.z); a.w = fmaf(r.w, ns, a.w);
            } else {
                a.x += r.x; a.y += r.y; a.z += r.z; a.w += r.w;
            }
        }

        float  nd = g_norm_dst[n];
        float4 bv = b[lane];
        float v0 = fmaxf(fmaf(a.x, nd, bv.x), 0.f);
        float v1 = fmaxf(fmaf(a.y, nd, bv.y), 0.f);
        float v2 = fmaxf(fmaf(a.z, nd, bv.z), 0.f);
        float v3 = fmaxf(fmaf(a.w, nd, bv.w), 0.f);

        if (EPI == 0) {
            float ns = g_norm_src[n];  // pre-scale for layer-2 gather
            out[(size_t)n * D4 + lane] = make_float4(v0 * ns, v1 * ns, v2 * ns, v3 * ns);
        } else {
            // non-negative floats: uint ordering == float ordering
            atomicMax(&smax[4 * lane + 0], __float_as_uint(v0));
            atomicMax(&smax[4 * lane + 1], __float_as_uint(v1));
            atomicMax(&smax[4 * lane + 2], __float_as_uint(v2));
            atomicMax(&smax[4 * lane + 3], __float_as_uint(v3));
        }
    }

    if (EPI == 1) {
        __syncthreads();
        if (t < D) atomicMax(&g_max[t], smax[t]);
    }
}

// --- head: out[1,2] = gmax @ Wl + bl -------------------------------------------
__global__ void final_kernel(const float* __restrict__ Wl,
                             const float* __restrict__ bl,
                             float* __restrict__ out) {
    int c = threadIdx.x;
    if (c < 2) {
        float acc = bl[c];
        #pragma unroll 8
        for (int k = 0; k < D; k++)
            acc += __uint_as_float(g_max[k]) * Wl[k * 2 + c];
        out[c] = acc;
    }
}

// --- side-stream + events, created once at static init (host objects only) -----
struct Aux {
    cudaStream_t s2  = nullptr;
    cudaEvent_t  evF = nullptr, evJ = nullptr;
    bool ok = false;
    Aux() {
        if (cudaStreamCreateWithFlags(&s2, cudaStreamNonBlocking) == cudaSuccess &&
            cudaEventCreateWithFlags(&evF, cudaEventDisableTiming) == cudaSuccess &&
            cudaEventCreateWithFlags(&evJ, cudaEventDisableTiming) == cudaSuccess)
            ok = true;
    }
};
static Aux g_aux;

extern "C" void kernel_launch(void* const* d_in, const int* in_sizes, int n_in,
                              void* d_out, int out_size) {
    const float* x   = (const float*)d_in[0];
    const int*   src = (const int*)  d_in[1];
    const int*   dst = (const int*)  d_in[2];
    const float* W1  = (const float*)d_in[3];
    const float* b1  = (const float*)d_in[4];
    const float* W2  = (const float*)d_in[5];
    const float* b2  = (const float*)d_in[6];
    const float* Wl  = (const float*)d_in[7];
    const float* bl  = (const float*)d_in[8];
    float* out = (float*)d_out;

    void *pxw, *ph1;
    cudaGetSymbolAddress(&pxw, g_xw);
    cudaGetSymbolAddress(&ph1, g_h1);
    float* xw = (float*)pxw;
    float* h1 = (float*)ph1;

    int dblocks = (NN + 15) / 16;
    int gblocks = (NN * 32 + 255) / 256;

    // --- fork: x@W1 on side stream, concurrent with the CSR build chain ---
    bool fork = g_aux.ok;
    if (fork) {
        cudaEventRecord(g_aux.evF, 0);
        cudaStreamWaitEvent(g_aux.s2, g_aux.evF, 0);
        dense_kernel<<<dblocks, dim3(96, 2), 0, g_aux.s2>>>(x, W1, xw);
        cudaEventRecord(g_aux.evJ, g_aux.s2);
    } else {
        dense_kernel<<<dblocks, dim3(96, 2)>>>(x, W1, xw);
    }

    // --- CSR build chain (main stream) ---
    zero_kernel <<<(NN + 255) / 256, 256>>>();
    deg_kernel  <<<(NE + 255) / 256, 256>>>(src, dst);
    scan1_kernel<<<SCAN_NB, 256>>>();
    scan2_kernel<<<SCAN_NB, 256>>>();
    fill_kernel <<<(NE + 255) / 256, 256>>>(src, dst);

    if (fork) cudaStreamWaitEvent(0, g_aux.evJ, 0);   // join before gather

    // Layer 1: h1 = relu(nd * sum_s ns[s]*xw[s] + b1) * ns
    gather_kernel<0><<<gblocks, 256>>>((const float4*)xw, (const float4*)b1,
                                       (float4*)h1);
    // Layer 2: xw = h1@W2 (h1 already ns-scaled); gather + fused maxpool
    dense_kernel<<<dblocks, dim3(96, 2)>>>(h1, W2, xw);
    gather_kernel<1><<<gblocks, 256>>>((const float4*)xw, (const float4*)b2,
                                       nullptr);

    final_kernel<<<1, 32>>>(Wl, bl, out);
}

// round 7
// speedup vs baseline: 1.0237x; 1.0182x over previous
#include <cuda_runtime.h>
#include <cuda_fp16.h>

// ---------------------------------------------------------------------------
// GCN_dgl: 2-layer symmetric-normalized GCN + max-pool readout + linear head
// R7: fp16 STORAGE for intermediates (xw1, h1, xw2) -> gather L2 bytes halved.
//     All arithmetic stays fp32 (GEMM accum, gather accum, norms, maxpool).
//     Gather unrolled x8; serial single-stream (overlap proven useless:
//     all kernels saturate the chip).
// ---------------------------------------------------------------------------

constexpr int NN = 50000;
constexpr int NE = 800000;
constexpr int D  = 96;
constexpr int DH4 = D / 4;                  // 24 half4-lanes per row (8B each)
constexpr int SCAN_NB = (NN + 255) / 256;   // 196 scan blocks

struct alignas(8) h4 { __half2 lo, hi; };   // 4 halves = 8 bytes

// Scratch (allocation-free: __device__ globals)
__device__ int          g_degi_out[NN];
__device__ int          g_degi_in[NN];
__device__ float        g_norm_src[NN];
__device__ float        g_norm_dst[NN];
__device__ int          g_offs[NN + 1];     // CSR row offsets (by dst)
__device__ int          g_blocksums[SCAN_NB];
__device__ int          g_fill[NN];
__device__ int          g_csr[NE];          // src index per CSR slot
__device__ __half       g_xw[(size_t)NN * D];  // GEMM output (fp16, reused)
__device__ __half       g_h1[(size_t)NN * D];  // layer-1 activations (ns-prescaled)
__device__ unsigned int g_max[D];           // uint-ordered non-negative floats

// --- zero all per-call counters ----------------------------------------------
__global__ void zero_kernel() {
    int i = blockIdx.x * blockDim.x + threadIdx.x;
    if (i < NN) { g_degi_out[i] = 0; g_degi_in[i] = 0; g_fill[i] = 0; }
    if (i < D)  g_max[i] = 0u;
}

// --- degree histogram ----------------------------------------------------------
__global__ void deg_kernel(const int* __restrict__ src, const int* __restrict__ dst) {
    int i = blockIdx.x * blockDim.x + threadIdx.x;
    if (i < NE) {
        atomicAdd(&g_degi_out[src[i]], 1);
        atomicAdd(&g_degi_in [dst[i]], 1);
    }
}

// --- scan pass 1: per-block exclusive scan of deg_in; norms fused --------------
__global__ void scan1_kernel() {
    __shared__ int sh[256];
    int t = threadIdx.x;
    int i = blockIdx.x * 256 + t;
    int v = (i < NN) ? g_degi_in[i] : 0;
    if (i < NN) {
        int dO = g_degi_out[i];
        g_norm_src[i] = (dO > 0) ? rsqrtf((float)dO) : 1.0f;
        g_norm_dst[i] = (v  > 0) ? rsqrtf((float)v)  : 1.0f;
    }
    sh[t] = v;
    __syncthreads();
    #pragma unroll
    for (int off = 1; off < 256; off <<= 1) {
        int a = (t >= off) ? sh[t - off] : 0;
        __syncthreads();
        sh[t] += a;
        __syncthreads();
    }
    if (i < NN) g_offs[i] = sh[t] - v;       // exclusive within block
    if (t == 255) g_blocksums[blockIdx.x] = sh[255];
}

// --- scan pass 2: every block redundantly scans the 196-entry spine ------------
__global__ void scan2_kernel() {
    __shared__ int sp[256];
    int t = threadIdx.x;
    int v = (t < SCAN_NB) ? g_blocksums[t] : 0;
    sp[t] = v;
    __syncthreads();
    #pragma unroll
    for (int off = 1; off < 256; off <<= 1) {
        int a = (t >= off) ? sp[t - off] : 0;
        __syncthreads();
        sp[t] += a;
        __syncthreads();
    }
    int prefix = (blockIdx.x > 0) ? sp[blockIdx.x - 1] : 0;
    int i = blockIdx.x * 256 + t;
    if (i < NN) g_offs[i] += prefix;
    if (i == 0) g_offs[NN] = NE;
}

// --- CSR bucket fill ------------------------------------------------------------
__global__ void fill_kernel(const int* __restrict__ src, const int* __restrict__ dst) {
    int e = blockIdx.x * blockDim.x + threadIdx.x;
    if (e < NE) {
        int d   = dst[e];
        int pos = g_offs[d] + atomicAdd(&g_fill[d], 1);
        g_csr[pos] = src[e];
    }
}

// --- dense GEMM: out_h = (in @ W) [* norm_src] ----------------------------------
// MODE 0: fp32 input x, epilogue scales by norm_src (pre-gather scaling)
// MODE 1: fp16 input h1 (already ns-scaled), no epilogue scale
// fp32 math throughout; output stored as fp16.
template <int MODE>
__global__ void __launch_bounds__(192)
dense_kernel(const void* __restrict__ in_, const float* __restrict__ W,
             __half* __restrict__ out) {
    __shared__ float  Ws[D * D];                 // [k][j]
    __shared__ float4 Rs4[2][8][DH4];            // node rows (fp32)

    int j = threadIdx.x;              // 0..95 output feature
    int y = threadIdx.y;              // 0..1  node sub-group
    int t = y * 96 + j;

    for (int idx = t; idx < D * D; idx += 192) Ws[idx] = W[idx];

    int n0 = blockIdx.x * 16 + y * 8;
    #pragma unroll
    for (int m = 0; m < 8; m++) {
        int n = n0 + m;
        float v = 0.f;
        if (n < NN) {
            if (MODE == 0) v = ((const float*)in_)[(size_t)n * D + j];
            else           v = __half2float(((const __half*)in_)[(size_t)n * D + j]);
        }
        ((float*)&Rs4[y][m][0])[j] = v;
    }
    __syncthreads();

    float acc[8];
    #pragma unroll
    for (int m = 0; m < 8; m++) acc[m] = 0.f;

    #pragma unroll 6
    for (int k4 = 0; k4 < DH4; k4++) {
        float w0 = Ws[(4 * k4 + 0) * D + j];
        float w1 = Ws[(4 * k4 + 1) * D + j];
        float w2 = Ws[(4 * k4 + 2) * D + j];
        float w3 = Ws[(4 * k4 + 3) * D + j];
        #pragma unroll
        for (int m = 0; m < 8; m++) {
            float4 r = Rs4[y][m][k4];
            acc[m] = fmaf(r.x, w0, acc[m]);
            acc[m] = fmaf(r.y, w1, acc[m]);
            acc[m] = fmaf(r.z, w2, acc[m]);
            acc[m] = fmaf(r.w, w3, acc[m]);
        }
    }

    #pragma unroll
    for (int m = 0; m < 8; m++) {
        int n = n0 + m;
        if (n < NN) {
            float v = acc[m];
            if (MODE == 0) v *= g_norm_src[n];
            out[(size_t)n * D + j] = __float2half_rn(v);
        }
    }
}

// --- pull-gather (fp16 rows, fp32 accum) + layer epilogue -----------------------
// One warp per node; lane l<24 owns features {4l..4l+3} (one 8B h4 per edge).
// EPI 0: out[n] = relu(agg*nd + b) * ns  stored fp16 (pre-scaled for layer 2)
// EPI 1: relu(agg*nd + b) -> block smem max -> global atomicMax
template <int EPI>
__global__ void __launch_bounds__(256)
gather_kernel(const h4* __restrict__ in, const float4* __restrict__ b,
              h4* __restrict__ out) {
    __shared__ unsigned int smax[D];
    int t = threadIdx.x;
    if (EPI == 1) {
        if (t < D) smax[t] = 0u;
        __syncthreads();
    }

    int n    = (blockIdx.x * 256 + t) >> 5;
    int lane = t & 31;

    if (n < NN && lane < DH4) {
        int p  = g_offs[n];
        int p1 = g_offs[n + 1];
        float4 a = make_float4(0.f, 0.f, 0.f, 0.f);

        for (; p + 8 <= p1; p += 8) {            // 8-wide unroll for MLP
            int s[8];
            #pragma unroll
            for (int i = 0; i < 8; i++) s[i] = g_csr[p + i];
            h4 r[8];
            #pragma unroll
            for (int i = 0; i < 8; i++) r[i] = in[(size_t)s[i] * DH4 + lane];
            #pragma unroll
            for (int i = 0; i < 8; i++) {
                float2 f0 = __half22float2(r[i].lo);
                float2 f1 = __half22float2(r[i].hi);
                a.x += f0.x; a.y += f0.y; a.z += f1.x; a.w += f1.y;
            }
        }
        for (; p < p1; ++p) {
            h4 r = in[(size_t)g_csr[p] * DH4 + lane];
            float2 f0 = __half22float2(r.lo);
            float2 f1 = __half22float2(r.hi);
            a.x += f0.x; a.y += f0.y; a.z += f1.x; a.w += f1.y;
        }

        float  nd = g_norm_dst[n];
        float4 bv = b[lane];
        float v0 = fmaxf(fmaf(a.x, nd, bv.x), 0.f);
        float v1 = fmaxf(fmaf(a.y, nd, bv.y), 0.f);
        float v2 = fmaxf(fmaf(a.z, nd, bv.z), 0.f);
        float v3 = fmaxf(fmaf(a.w, nd, bv.w), 0.f);

        if (EPI == 0) {
            float ns = g_norm_src[n];            // pre-scale for layer-2 gather
            h4 o;
            o.lo = __floats2half2_rn(v0 * ns, v1 * ns);
            o.hi = __floats2half2_rn(v2 * ns, v3 * ns);
            out[(size_t)n * DH4 + lane] = o;
        } else {
            // non-negative floats: uint ordering == float ordering
            atomicMax(&smax[4 * lane + 0], __float_as_uint(v0));
            atomicMax(&smax[4 * lane + 1], __float_as_uint(v1));
            atomicMax(&smax[4 * lane + 2], __float_as_uint(v2));
            atomicMax(&smax[4 * lane + 3], __float_as_uint(v3));
        }
    }

    if (EPI == 1) {
        __syncthreads();
        if (t < D) atomicMax(&g_max[t], smax[t]);
    }
}

// --- head: out[1,2] = gmax @ Wl + bl ---------------------------------------------
__global__ void final_kernel(const float* __restrict__ Wl,
                             const float* __restrict__ bl,
                             float* __restrict__ out) {
    int c = threadIdx.x;
    if (c < 2) {
        float acc = bl[c];
        #pragma unroll 8
        for (int k = 0; k < D; k++)
            acc += __uint_as_float(g_max[k]) * Wl[k * 2 + c];
        out[c] = acc;
    }
}

extern "C" void kernel_launch(void* const* d_in, const int* in_sizes, int n_in,
                              void* d_out, int out_size) {
    const float* x   = (const float*)d_in[0];
    const int*   src = (const int*)  d_in[1];
    const int*   dst = (const int*)  d_in[2];
    const float* W1  = (const float*)d_in[3];
    const float* b1  = (const float*)d_in[4];
    const float* W2  = (const float*)d_in[5];
    const float* b2  = (const float*)d_in[6];
    const float* Wl  = (const float*)d_in[7];
    const float* bl  = (const float*)d_in[8];
    float* out = (float*)d_out;

    void *pxw, *ph1;
    cudaGetSymbolAddress(&pxw, g_xw);
    cudaGetSymbolAddress(&ph1, g_h1);
    __half* xw = (__half*)pxw;
    __half* h1 = (__half*)ph1;

    int dblocks = (NN + 15) / 16;
    int gblocks = (NN * 32 + 255) / 256;     // one warp per node

    // CSR build chain
    zero_kernel <<<(NN + 255) / 256, 256>>>();
    deg_kernel  <<<(NE + 255) / 256, 256>>>(src, dst);
    scan1_kernel<<<SCAN_NB, 256>>>();
    scan2_kernel<<<SCAN_NB, 256>>>();
    fill_kernel <<<(NE + 255) / 256, 256>>>(src, dst);

    // Layer 1: xw = (x@W1)*ns (fp16);  h1 = relu(nd*gather(xw) + b1)*ns (fp16)
    dense_kernel<0><<<dblocks, dim3(96, 2)>>>(x, W1, xw);
    gather_kernel<0><<<gblocks, 256>>>((const h4*)xw, (const float4*)b1, (h4*)h1);

    // Layer 2: xw = h1@W2 (fp16); gather + fused maxpool
    dense_kernel<1><<<dblocks, dim3(96, 2)>>>(h1, W2, xw);
    gather_kernel<1><<<gblocks, 256>>>((const h4*)xw, (const float4*)b2, nullptr);

    final_kernel<<<1, 32>>>(Wl, bl, out);
}

// round 8
// speedup vs baseline: 1.6660x; 1.6274x over previous
#include <cuda_runtime.h>
#include <cuda_fp16.h>
#include <cstdint>

// ---------------------------------------------------------------------------
// GCN_dgl: 2-layer symmetric-normalized GCN + max-pool readout + linear head
// R8: dense GEMMs moved to HMMA tensor cores (mma.sync m16n8k16, fp16 in,
//     fp32 accum). Intermediates stay fp16 (R6). Gather/CSR unchanged.
// ---------------------------------------------------------------------------

constexpr int NN = 50000;
constexpr int NE = 800000;
constexpr int D  = 96;
constexpr int DH4 = D / 4;                  // 24 8B-lanes per fp16 row
constexpr int SCAN_NB = (NN + 255) / 256;   // 196 scan blocks
constexpr int LDS = 104;                    // smem half-stride (208B, 16B-aligned)

struct alignas(8) h4 { __half2 lo, hi; };   // 4 halves = 8 bytes

// Scratch (allocation-free: __device__ globals)
__device__ int          g_degi_out[NN];
__device__ int          g_degi_in[NN];
__device__ float        g_norm_src[NN];
__device__ float        g_norm_dst[NN];
__device__ int          g_offs[NN + 1];
__device__ int          g_blocksums[SCAN_NB];
__device__ int          g_fill[NN];
__device__ int          g_csr[NE];
__device__ __half       g_xw[(size_t)NN * D];  // GEMM output (fp16, reused)
__device__ __half       g_h1[(size_t)NN * D];  // layer-1 activations (ns-prescaled)
__device__ unsigned int g_max[D];

// --- mma/ldmatrix primitives --------------------------------------------------
__device__ __forceinline__ void ldsm_x4(uint32_t& r0, uint32_t& r1, uint32_t& r2,
                                        uint32_t& r3, uint32_t addr) {
    asm volatile("ldmatrix.sync.aligned.m8n8.x4.shared.b16 {%0,%1,%2,%3}, [%4];"
                 : "=r"(r0), "=r"(r1), "=r"(r2), "=r"(r3) : "r"(addr));
}
__device__ __forceinline__ void ldsm_x2_trans(uint32_t& r0, uint32_t& r1, uint32_t addr) {
    asm volatile("ldmatrix.sync.aligned.m8n8.x2.trans.shared.b16 {%0,%1}, [%2];"
                 : "=r"(r0), "=r"(r1) : "r"(addr));
}
__device__ __forceinline__ void mma16816(float& d0, float& d1, float& d2, float& d3,
                                         uint32_t a0, uint32_t a1, uint32_t a2,
                                         uint32_t a3, uint32_t b0, uint32_t b1) {
    asm volatile(
        "mma.sync.aligned.m16n8k16.row.col.f32.f16.f16.f32 "
        "{%0,%1,%2,%3},{%4,%5,%6,%7},{%8,%9},{%0,%1,%2,%3};"
        : "+f"(d0), "+f"(d1), "+f"(d2), "+f"(d3)
        : "r"(a0), "r"(a1), "r"(a2), "r"(a3), "r"(b0), "r"(b1));
}

// --- zero all per-call counters -------------------------------------------------
__global__ void zero_kernel() {
    int i = blockIdx.x * blockDim.x + threadIdx.x;
    if (i < NN) { g_degi_out[i] = 0; g_degi_in[i] = 0; g_fill[i] = 0; }
    if (i < D)  g_max[i] = 0u;
}

// --- degree histogram ------------------------------------------------------------
__global__ void deg_kernel(const int* __restrict__ src, const int* __restrict__ dst) {
    int i = blockIdx.x * blockDim.x + threadIdx.x;
    if (i < NE) {
        atomicAdd(&g_degi_out[src[i]], 1);
        atomicAdd(&g_degi_in [dst[i]], 1);
    }
}

// --- scan pass 1 + norms ----------------------------------------------------------
__global__ void scan1_kernel() {
    __shared__ int sh[256];
    int t = threadIdx.x;
    int i = blockIdx.x * 256 + t;
    int v = (i < NN) ? g_degi_in[i] : 0;
    if (i < NN) {
        int dO = g_degi_out[i];
        g_norm_src[i] = (dO > 0) ? rsqrtf((float)dO) : 1.0f;
        g_norm_dst[i] = (v  > 0) ? rsqrtf((float)v)  : 1.0f;
    }
    sh[t] = v;
    __syncthreads();
    #pragma unroll
    for (int off = 1; off < 256; off <<= 1) {
        int a = (t >= off) ? sh[t - off] : 0;
        __syncthreads();
        sh[t] += a;
        __syncthreads();
    }
    if (i < NN) g_offs[i] = sh[t] - v;
    if (t == 255) g_blocksums[blockIdx.x] = sh[255];
}

// --- scan pass 2 (redundant spine scan per block) -----------------------------------
__global__ void scan2_kernel() {
    __shared__ int sp[256];
    int t = threadIdx.x;
    int v = (t < SCAN_NB) ? g_blocksums[t] : 0;
    sp[t] = v;
    __syncthreads();
    #pragma unroll
    for (int off = 1; off < 256; off <<= 1) {
        int a = (t >= off) ? sp[t - off] : 0;
        __syncthreads();
        sp[t] += a;
        __syncthreads();
    }
    int prefix = (blockIdx.x > 0) ? sp[blockIdx.x - 1] : 0;
    int i = blockIdx.x * 256 + t;
    if (i < NN) g_offs[i] += prefix;
    if (i == 0) g_offs[NN] = NE;
}

// --- CSR bucket fill ------------------------------------------------------------------
__global__ void fill_kernel(const int* __restrict__ src, const int* __restrict__ dst) {
    int e = blockIdx.x * blockDim.x + threadIdx.x;
    if (e < NE) {
        int d   = dst[e];
        int pos = g_offs[d] + atomicAdd(&g_fill[d], 1);
        g_csr[pos] = src[e];
    }
}

// --- tensor-core dense GEMM: out_h = (in @ W) [* norm_src] ------------------------------
// Block: 4 warps, 64 rows x 96 cols. A per-warp 16x96 fp16 smem tile; W (fp32)
// converted to fp16 smem. mma.sync m16n8k16, fp32 accumulators.
// MODE 0: fp32 input (x), epilogue scales rows by norm_src. MODE 1: fp16 input.
template <int MODE>
__global__ void __launch_bounds__(128)
dense_mma(const void* __restrict__ in_, const float* __restrict__ W,
          __half* __restrict__ out) {
    __shared__ alignas(16) __half Bs[96 * LDS];
    __shared__ alignas(16) __half As[4][16 * LDS];

    int tid = threadIdx.x, wid = tid >> 5, lane = tid & 31;

    // Stage W (96x96 fp32 -> fp16), 12 8-col chunks per row
    for (int c = tid; c < 96 * 12; c += 128) {
        int r = c / 12, c8 = c % 12;
        const float4* wp = (const float4*)(W + r * 96 + c8 * 8);
        float4 f0 = wp[0], f1 = wp[1];
        __half hb[8] = {__float2half_rn(f0.x), __float2half_rn(f0.y),
                        __float2half_rn(f0.z), __float2half_rn(f0.w),
                        __float2half_rn(f1.x), __float2half_rn(f1.y),
                        __float2half_rn(f1.z), __float2half_rn(f1.w)};
        *(uint4*)&Bs[r * LDS + c8 * 8] = *(uint4*)hb;
    }

    // Stage this warp's 16 A rows
    int rowBase = blockIdx.x * 64 + wid * 16;
    for (int c = lane; c < 16 * 12; c += 32) {
        int r = c / 12, c8 = c % 12;
        int n = rowBase + r;
        __half hb[8];
        if (n < NN) {
            if (MODE == 0) {
                const float4* xp = (const float4*)((const float*)in_ + (size_t)n * D + c8 * 8);
                float4 f0 = xp[0], f1 = xp[1];
                hb[0] = __float2half_rn(f0.x); hb[1] = __float2half_rn(f0.y);
                hb[2] = __float2half_rn(f0.z); hb[3] = __float2half_rn(f0.w);
                hb[4] = __float2half_rn(f1.x); hb[5] = __float2half_rn(f1.y);
                hb[6] = __float2half_rn(f1.z); hb[7] = __float2half_rn(f1.w);
            } else {
                *(uint4*)hb = *(const uint4*)((const __half*)in_ + (size_t)n * D + c8 * 8);
            }
        } else {
            #pragma unroll
            for (int q = 0; q < 8; q++) hb[q] = __float2half_rn(0.f);
        }
        *(uint4*)&As[wid][r * LDS + c8 * 8] = *(uint4*)hb;
    }
    __syncthreads();

    float d[12][4];
    #pragma unroll
    for (int j = 0; j < 12; j++) { d[j][0] = d[j][1] = d[j][2] = d[j][3] = 0.f; }

    uint32_t aBase = (uint32_t)__cvta_generic_to_shared(&As[wid][0]);
    uint32_t bBase = (uint32_t)__cvta_generic_to_shared(&Bs[0]);

    #pragma unroll
    for (int k = 0; k < 6; k++) {
        uint32_t a0, a1, a2, a3;
        uint32_t aAddr = aBase + (uint32_t)(((lane & 15) * LDS + (lane >> 4) * 8 + k * 16) * 2);
        ldsm_x4(a0, a1, a2, a3, aAddr);
        #pragma unroll
        for (int j = 0; j < 12; j++) {
            uint32_t b0, b1;
            uint32_t bAddr = bBase + (uint32_t)(((k * 16 + (lane & 15)) * LDS + j * 8) * 2);
            ldsm_x2_trans(b0, b1, bAddr);
            mma16816(d[j][0], d[j][1], d[j][2], d[j][3], a0, a1, a2, a3, b0, b1);
        }
    }

    // Epilogue: thread owns rows {g, g+8}, cols {2q, 2q+1} of each 8-col tile
    int g = lane >> 2, q = lane & 3;
    int r0 = rowBase + g, r1 = rowBase + g + 8;
    float ns0 = 1.f, ns1 = 1.f;
    if (MODE == 0) {
        if (r0 < NN) ns0 = g_norm_src[r0];
        if (r1 < NN) ns1 = g_norm_src[r1];
    }
    #pragma unroll
    for (int j = 0; j < 12; j++) {
        int col = j * 8 + q * 2;
        if (r0 < NN)
            *(__half2*)&out[(size_t)r0 * D + col] = __floats2half2_rn(d[j][0] * ns0, d[j][1] * ns0);
        if (r1 < NN)
            *(__half2*)&out[(size_t)r1 * D + col] = __floats2half2_rn(d[j][2] * ns1, d[j][3] * ns1);
    }
}

// --- pull-gather (fp16 rows, fp32 accum) + layer epilogue ---------------------------
template <int EPI>
__global__ void __launch_bounds__(256)
gather_kernel(const h4* __restrict__ in, const float4* __restrict__ b,
              h4* __restrict__ out) {
    __shared__ unsigned int smax[D];
    int t = threadIdx.x;
    if (EPI == 1) {
        if (t < D) smax[t] = 0u;
        __syncthreads();
    }

    int n    = (blockIdx.x * 256 + t) >> 5;
    int lane = t & 31;

    if (n < NN && lane < DH4) {
        int p  = g_offs[n];
        int p1 = g_offs[n + 1];
        float4 a = make_float4(0.f, 0.f, 0.f, 0.f);

        for (; p + 8 <= p1; p += 8) {
            int s[8];
            #pragma unroll
            for (int i = 0; i < 8; i++) s[i] = g_csr[p + i];
            h4 r[8];
            #pragma unroll
            for (int i = 0; i < 8; i++) r[i] = in[(size_t)s[i] * DH4 + lane];
            #pragma unroll
            for (int i = 0; i < 8; i++) {
                float2 f0 = __half22float2(r[i].lo);
                float2 f1 = __half22float2(r[i].hi);
                a.x += f0.x; a.y += f0.y; a.z += f1.x; a.w += f1.y;
            }
        }
        for (; p < p1; ++p) {
            h4 r = in[(size_t)g_csr[p] * DH4 + lane];
            float2 f0 = __half22float2(r.lo);
            float2 f1 = __half22float2(r.hi);
            a.x += f0.x; a.y += f0.y; a.z += f1.x; a.w += f1.y;
        }

        float  nd = g_norm_dst[n];
        float4 bv = b[lane];
        float v0 = fmaxf(fmaf(a.x, nd, bv.x), 0.f);
        float v1 = fmaxf(fmaf(a.y, nd, bv.y), 0.f);
        float v2 = fmaxf(fmaf(a.z, nd, bv.z), 0.f);
        float v3 = fmaxf(fmaf(a.w, nd, bv.w), 0.f);

        if (EPI == 0) {
            float ns = g_norm_src[n];
            h4 o;
            o.lo = __floats2half2_rn(v0 * ns, v1 * ns);
            o.hi = __floats2half2_rn(v2 * ns, v3 * ns);
            out[(size_t)n * DH4 + lane] = o;
        } else {
            atomicMax(&smax[4 * lane + 0], __float_as_uint(v0));
            atomicMax(&smax[4 * lane + 1], __float_as_uint(v1));
            atomicMax(&smax[4 * lane + 2], __float_as_uint(v2));
            atomicMax(&smax[4 * lane + 3], __float_as_uint(v3));
        }
    }

    if (EPI == 1) {
        __syncthreads();
        if (t < D) atomicMax(&g_max[t], smax[t]);
    }
}

// --- head: out[1,2] = gmax @ Wl + bl ---------------------------------------------------
__global__ void final_kernel(const float* __restrict__ Wl,
                             const float* __restrict__ bl,
                             float* __restrict__ out) {
    int c = threadIdx.x;
    if (c < 2) {
        float acc = bl[c];
        #pragma unroll 8
        for (int k = 0; k < D; k++)
            acc += __uint_as_float(g_max[k]) * Wl[k * 2 + c];
        out[c] = acc;
    }
}

extern "C" void kernel_launch(void* const* d_in, const int* in_sizes, int n_in,
                              void* d_out, int out_size) {
    const float* x   = (const float*)d_in[0];
    const int*   src = (const int*)  d_in[1];
    const int*   dst = (const int*)  d_in[2];
    const float* W1  = (const float*)d_in[3];
    const float* b1  = (const float*)d_in[4];
    const float* W2  = (const float*)d_in[5];
    const float* b2  = (const float*)d_in[6];
    const float* Wl  = (const float*)d_in[7];
    const float* bl  = (const float*)d_in[8];
    float* out = (float*)d_out;

    void *pxw, *ph1;
    cudaGetSymbolAddress(&pxw, g_xw);
    cudaGetSymbolAddress(&ph1, g_h1);
    __half* xw = (__half*)pxw;
    __half* h1 = (__half*)ph1;

    int mblocks = (NN + 63) / 64;            // 782 HMMA blocks
    int gblocks = (NN * 32 + 255) / 256;     // one warp per node

    // CSR build chain
    zero_kernel <<<(NN + 255) / 256, 256>>>();
    deg_kernel  <<<(NE + 255) / 256, 256>>>(src, dst);
    scan1_kernel<<<SCAN_NB, 256>>>();
    scan2_kernel<<<SCAN_NB, 256>>>();
    fill_kernel <<<(NE + 255) / 256, 256>>>(src, dst);

    // Layer 1: xw = (x@W1)*ns (fp16, HMMA);  h1 = relu(nd*gather(xw)+b1)*ns
    dense_mma<0><<<mblocks, 128>>>(x, W1, xw);
    gather_kernel<0><<<gblocks, 256>>>((const h4*)xw, (const float4*)b1, (h4*)h1);

    // Layer 2: xw = h1@W2 (HMMA); gather + fused maxpool
    dense_mma<1><<<mblocks, 128>>>(h1, W2, xw);
    gather_kernel<1><<<gblocks, 256>>>((const h4*)xw, (const float4*)b2, nullptr);

    final_kernel<<<1, 32>>>(Wl, bl, out);
}